// round 1
// baseline (speedup 1.0000x reference)
#include <cuda_runtime.h>
#include <cstdint>
#include <cstdio>

// ---------------- problem constants ----------------
#define NN      100000
#define EE      1600000
#define NF      128
#define NCLASS  40
#define BN_EPS  1e-5f

// ---------------- device scratch (no allocs allowed) ----------------
__device__ int   g_eidx[2 * EE];          // normalized int32 edge index (src | dst)
__device__ int   g_flag[1];               // dtype flag: 1 -> input was int32
__device__ int   g_deg[NN];
__device__ int   g_tmp[NN];               // block-inclusive scan
__device__ int   g_bsum[256];
__device__ int   g_boff[256];
__device__ int   g_off[NN + 1];
__device__ int   g_cur[NN];
__device__ int   g_csr[EE];

__device__ float g_agg [NN * NF];
__device__ float g_h1  [NN * NF];
__device__ float g_h2  [NN * NF];
__device__ float g_p   [NN * 80];         // conv2 projected [P_l | P_r]
__device__ float g_oraw[NN * NCLASS];
__device__ float g_bc1 [256 * 128];       // k-major concat weights conv1
__device__ float g_bcx [256 * 128];       // conv_x
__device__ float g_bc2 [128 * 128];       // conv2 (cols 0..39 W2l, 40..79 W2r, rest 0)
__device__ float g_stats[256];            // [sum(0..127) | sumsq(128..255)]
__device__ float g_scale[128];
__device__ float g_shift[128];

// ---------------- edge-index dtype detect + convert ----------------
__global__ void detect_dtype_kernel(const void* p, int E, int n_nodes) {
    if (threadIdx.x == 0 && blockIdx.x == 0) {
        const long long* q = (const long long*)p;
        int m = E < 512 ? E : 512;
        int bad = 0;
        for (int i = 0; i < m; i++) {
            long long v = q[i];
            if (v < 0 || v >= (long long)n_nodes) bad = 1;
        }
        g_flag[0] = bad;  // bad under int64 view => data is really int32
    }
}

__global__ void convert_idx_kernel(const void* p, int twoE) {
    int is32 = g_flag[0];
    for (int i = blockIdx.x * blockDim.x + threadIdx.x; i < twoE;
         i += gridDim.x * blockDim.x) {
        int v;
        if (is32) v = ((const int*)p)[i];
        else      v = (int)((const long long*)p)[i];
        g_eidx[i] = v;
    }
}

// ---------------- CSR build ----------------
__global__ void zero_int_kernel(int* p, int n) {
    for (int i = blockIdx.x * blockDim.x + threadIdx.x; i < n;
         i += gridDim.x * blockDim.x) p[i] = 0;
}

__global__ void count_deg_kernel(int E) {
    const int* dst = g_eidx + E;
    for (int e = blockIdx.x * blockDim.x + threadIdx.x; e < E;
         e += gridDim.x * blockDim.x) {
        atomicAdd(&g_deg[dst[e]], 1);
    }
}

__global__ void scan1_kernel(int n) {
    __shared__ int sh[512];
    int i = blockIdx.x * 512 + threadIdx.x;
    int v = (i < n) ? g_deg[i] : 0;
    sh[threadIdx.x] = v;
    __syncthreads();
    #pragma unroll
    for (int s = 1; s < 512; s <<= 1) {
        int t = (threadIdx.x >= s) ? sh[threadIdx.x - s] : 0;
        __syncthreads();
        sh[threadIdx.x] += t;
        __syncthreads();
    }
    if (i < n) g_tmp[i] = sh[threadIdx.x];
    if (threadIdx.x == 511) g_bsum[blockIdx.x] = sh[511];
}

__global__ void scan2_kernel(int nb) {
    __shared__ int sh[256];
    int v = (threadIdx.x < nb) ? g_bsum[threadIdx.x] : 0;
    sh[threadIdx.x] = v;
    __syncthreads();
    #pragma unroll
    for (int s = 1; s < 256; s <<= 1) {
        int t = (threadIdx.x >= s) ? sh[threadIdx.x - s] : 0;
        __syncthreads();
        sh[threadIdx.x] += t;
        __syncthreads();
    }
    if (threadIdx.x < nb) g_boff[threadIdx.x] = sh[threadIdx.x] - v;  // exclusive
}

__global__ void scan3_kernel(int n) {
    for (int i = blockIdx.x * blockDim.x + threadIdx.x; i < n;
         i += gridDim.x * blockDim.x) {
        int incl = g_tmp[i] + g_boff[i >> 9];
        int excl = incl - g_deg[i];
        g_off[i] = excl;
        g_cur[i] = excl;
        if (i == n - 1) g_off[n] = incl;
    }
}

__global__ void fill_csr_kernel(int E) {
    const int* src = g_eidx;
    const int* dst = g_eidx + E;
    for (int e = blockIdx.x * blockDim.x + threadIdx.x; e < E;
         e += gridDim.x * blockDim.x) {
        int pos = atomicAdd(&g_cur[dst[e]], 1);
        g_csr[pos] = src[e];
    }
}

// ---------------- weight prep (k-major concat) ----------------
__global__ void prep_dual_w_kernel(const float* __restrict__ Wl,
                                   const float* __restrict__ Wr,
                                   float* __restrict__ out) {  // [256][128]
    for (int idx = blockIdx.x * blockDim.x + threadIdx.x; idx < 256 * 128;
         idx += gridDim.x * blockDim.x) {
        int k = idx >> 7, j = idx & 127;
        out[idx] = (k < 128) ? Wl[j * 128 + k] : Wr[j * 128 + (k - 128)];
    }
}

__global__ void prep_w2_kernel(const float* __restrict__ W2l,
                               const float* __restrict__ W2r) {  // g_bc2[128][128]
    for (int idx = blockIdx.x * blockDim.x + threadIdx.x; idx < 128 * 128;
         idx += gridDim.x * blockDim.x) {
        int k = idx >> 7, j = idx & 127;
        float v = 0.f;
        if (j < 40)       v = W2l[j * 128 + k];
        else if (j < 80)  v = W2r[(j - 40) * 128 + k];
        g_bc2[idx] = v;
    }
}

// ---------------- mean aggregation, 128-wide ----------------
__global__ void agg_mean128_kernel(const float* __restrict__ X,
                                   float* __restrict__ OUT, int n) {
    int node = blockIdx.x;
    if (node >= n) return;
    int tid = threadIdx.x;
    int s0 = g_off[node], s1 = g_off[node + 1];
    __shared__ int nb[128];
    float acc = 0.f;
    for (int base = s0; base < s1; base += 128) {
        int c = s1 - base; if (c > 128) c = 128;
        __syncthreads();
        if (tid < c) nb[tid] = g_csr[base + tid];
        __syncthreads();
        #pragma unroll 4
        for (int i = 0; i < c; i++) {
            acc += X[(size_t)nb[i] * NF + tid];
        }
    }
    int deg = s1 - s0;
    float inv = deg > 0 ? 1.f / (float)deg : 0.f;
    OUT[(size_t)node * NF + tid] = acc * inv;
}

// ---------------- conv2: agg 40-wide + combine + bias ----------------
__global__ void agg40_combine_kernel(const float* __restrict__ b2, int n) {
    int node = blockIdx.x;
    if (node >= n) return;
    int tid = threadIdx.x;  // blockDim 64, active tid<40
    int s0 = g_off[node], s1 = g_off[node + 1];
    __shared__ int nb[64];
    float acc = 0.f;
    for (int base = s0; base < s1; base += 64) {
        int c = s1 - base; if (c > 64) c = 64;
        __syncthreads();
        if (tid < c) nb[tid] = g_csr[base + tid];
        __syncthreads();
        if (tid < NCLASS) {
            #pragma unroll 4
            for (int i = 0; i < c; i++) {
                acc += g_p[(size_t)nb[i] * 80 + tid];
            }
        }
    }
    if (tid < NCLASS) {
        int deg = s1 - s0;
        float inv = deg > 0 ? 1.f / (float)deg : 0.f;
        g_oraw[(size_t)node * NCLASS + tid] =
            acc * inv + g_p[(size_t)node * 80 + 40 + tid] + b2[tid];
    }
}

// ---------------- tiled fp32 GEMM: C[M,ncol] = concat(A1,A2)[M,K] @ B[K,128] ----------------
__global__ __launch_bounds__(256)
void gemm_tiled_kernel(const float* __restrict__ A1, const float* __restrict__ A2,
                       const float* __restrict__ B, const float* __restrict__ bias,
                       float* __restrict__ C, int M, int K, int ncol, int ldc,
                       int relu) {
    __shared__ float As[16][132];
    __shared__ float Bs[16][128];
    int tid = threadIdx.x;
    int row0 = blockIdx.x * 128;
    int tx = tid & 15, ty = tid >> 4;
    float acc[8][8];
    #pragma unroll
    for (int m = 0; m < 8; m++)
        #pragma unroll
        for (int n2 = 0; n2 < 8; n2++) acc[m][n2] = 0.f;

    for (int k0 = 0; k0 < K; k0 += 16) {
        #pragma unroll
        for (int l = 0; l < 8; l++) {
            int idx = l * 256 + tid;
            int r = idx >> 4, kk = idx & 15;
            int kg = k0 + kk;
            const float* Ap = (kg < 128) ? A1 : A2;
            int kloc = kg & 127;
            int rg = row0 + r;
            As[kk][r] = (rg < M) ? Ap[(size_t)rg * 128 + kloc] : 0.f;
        }
        #pragma unroll
        for (int l = 0; l < 8; l++) {
            int idx = l * 256 + tid;
            int kk = idx >> 7, jj = idx & 127;
            Bs[kk][jj] = B[(size_t)(k0 + kk) * 128 + jj];
        }
        __syncthreads();
        #pragma unroll
        for (int kk = 0; kk < 16; kk++) {
            float ra[8], rb[8];
            #pragma unroll
            for (int m = 0; m < 8; m++) ra[m] = As[kk][ty * 8 + m];
            #pragma unroll
            for (int n2 = 0; n2 < 8; n2++) rb[n2] = Bs[kk][tx * 8 + n2];
            #pragma unroll
            for (int m = 0; m < 8; m++)
                #pragma unroll
                for (int n2 = 0; n2 < 8; n2++) acc[m][n2] += ra[m] * rb[n2];
        }
        __syncthreads();
    }

    #pragma unroll
    for (int m = 0; m < 8; m++) {
        int rg = row0 + ty * 8 + m;
        if (rg >= M) continue;
        #pragma unroll
        for (int n2 = 0; n2 < 8; n2++) {
            int c = tx * 8 + n2;
            if (c < ncol) {
                float v = acc[m][n2];
                if (bias) v += bias[c];
                if (relu) v = fmaxf(v, 0.f);
                C[(size_t)rg * ldc + c] = v;
            }
        }
    }
}

// ---------------- BatchNorm ----------------
__global__ void zero_stats_kernel() {
    if (threadIdx.x < 256) g_stats[threadIdx.x] = 0.f;
}

__global__ void bn_stats_kernel(const float* __restrict__ X, int M, int F, int ld) {
    int col = threadIdx.x;
    if (col >= F) return;
    float s = 0.f, s2 = 0.f;
    for (int r = blockIdx.x; r < M; r += gridDim.x) {
        float v = X[(size_t)r * ld + col];
        s += v; s2 += v * v;
    }
    atomicAdd(&g_stats[col], s);
    atomicAdd(&g_stats[128 + col], s2);
}

__global__ void bn_finalize_kernel(const float* __restrict__ gamma,
                                   const float* __restrict__ beta,
                                   int F, float invM) {
    int c = threadIdx.x;
    if (c < F) {
        float mu  = g_stats[c] * invM;
        float var = g_stats[128 + c] * invM - mu * mu;
        float sc  = gamma[c] * rsqrtf(var + BN_EPS);
        g_scale[c] = sc;
        g_shift[c] = beta[c] - mu * sc;
    }
}

__global__ void bn_apply_kernel(const float* __restrict__ X, float* __restrict__ Y,
                                int total, int F, int relu) {
    for (int i = blockIdx.x * blockDim.x + threadIdx.x; i < total;
         i += gridDim.x * blockDim.x) {
        int c = i % F;
        float v = X[i] * g_scale[c] + g_shift[c];
        if (relu) v = fmaxf(v, 0.f);
        Y[i] = v;
    }
}

// ---------------- launcher ----------------
extern "C" void kernel_launch(void* const* d_in, const int* in_sizes, int n_in,
                              void* d_out, int out_size) {
    const float* x   = (const float*)d_in[0];
    const void*  ei  = d_in[1];
    const float* W1l = (const float*)d_in[2];
    const float* b1  = (const float*)d_in[3];
    const float* W1r = (const float*)d_in[4];
    const float* Wxl = (const float*)d_in[5];
    const float* bx  = (const float*)d_in[6];
    const float* Wxr = (const float*)d_in[7];
    const float* W2l = (const float*)d_in[8];
    const float* b2  = (const float*)d_in[9];
    const float* W2r = (const float*)d_in[10];
    const float* g3  = (const float*)d_in[11];
    const float* be3 = (const float*)d_in[12];
    const float* g2  = (const float*)d_in[13];
    const float* be2 = (const float*)d_in[14];
    float* out = (float*)d_out;

    const int N    = in_sizes[0] / NF;      // 100000
    const int twoE = in_sizes[1];
    const int E    = twoE / 2;              // 1600000

    float *p_agg, *p_h1, *p_h2, *p_p, *p_oraw, *p_bc1, *p_bcx, *p_bc2;
    int   *p_deg;
    cudaGetSymbolAddress((void**)&p_agg,  g_agg);
    cudaGetSymbolAddress((void**)&p_h1,   g_h1);
    cudaGetSymbolAddress((void**)&p_h2,   g_h2);
    cudaGetSymbolAddress((void**)&p_p,    g_p);
    cudaGetSymbolAddress((void**)&p_oraw, g_oraw);
    cudaGetSymbolAddress((void**)&p_bc1,  g_bc1);
    cudaGetSymbolAddress((void**)&p_bcx,  g_bcx);
    cudaGetSymbolAddress((void**)&p_bc2,  g_bc2);
    cudaGetSymbolAddress((void**)&p_deg,  g_deg);

    const int nb = (N + 511) / 512;        // scan blocks (196)
    const int gemm_blocks = (N + 127) / 128;

    // --- edge index normalize ---
    detect_dtype_kernel<<<1, 32>>>(ei, E, N);
    convert_idx_kernel<<<2048, 256>>>(ei, twoE);

    // --- CSR build ---
    zero_int_kernel<<<512, 256>>>(p_deg, N);
    count_deg_kernel<<<2048, 256>>>(E);
    scan1_kernel<<<nb, 512>>>(N);
    scan2_kernel<<<1, 256>>>(nb);
    scan3_kernel<<<512, 256>>>(N);
    fill_csr_kernel<<<2048, 256>>>(E);

    // --- weight prep ---
    prep_dual_w_kernel<<<128, 256>>>(W1l, W1r, p_bc1);
    prep_dual_w_kernel<<<128, 256>>>(Wxl, Wxr, p_bcx);
    prep_w2_kernel<<<64, 256>>>(W2l, W2r);

    // --- conv1 + relu ---
    agg_mean128_kernel<<<N, 128>>>(x, p_agg, N);
    gemm_tiled_kernel<<<gemm_blocks, 256>>>(p_agg, x, p_bc1, b1, p_h1,
                                            N, 256, 128, 128, 1);

    // --- conv_x ---
    agg_mean128_kernel<<<N, 128>>>(p_h1, p_agg, N);
    gemm_tiled_kernel<<<gemm_blocks, 256>>>(p_agg, p_h1, p_bcx, bx, p_h2,
                                            N, 256, 128, 128, 0);

    // --- BN3 + relu (in place) ---
    zero_stats_kernel<<<1, 256>>>();
    bn_stats_kernel<<<1024, 128>>>(p_h2, N, 128, 128);
    bn_finalize_kernel<<<1, 128>>>(g3, be3, 128, 1.f / (float)N);
    bn_apply_kernel<<<2048, 256>>>(p_h2, p_h2, N * NF, 128, 1);

    // --- conv2: project first (linearity), then 40-wide aggregate ---
    gemm_tiled_kernel<<<gemm_blocks, 256>>>(p_h2, p_h2, p_bc2, nullptr, p_p,
                                            N, 128, 80, 80, 0);
    agg40_combine_kernel<<<N, 64>>>(b2, N);

    // --- BN2 -> output ---
    zero_stats_kernel<<<1, 256>>>();
    bn_stats_kernel<<<1024, 64>>>(p_oraw, N, NCLASS, NCLASS);
    bn_finalize_kernel<<<1, 64>>>(g2, be2, NCLASS, 1.f / (float)N);
    bn_apply_kernel<<<2048, 256>>>(p_oraw, out, N * NCLASS, NCLASS, 0);
}

// round 2
// speedup vs baseline: 1.2291x; 1.2291x over previous
#include <cuda_runtime.h>
#include <cstdint>
#include <cstdio>

// ---------------- problem constants ----------------
#define NN      100000
#define EE      1600000
#define NF      128
#define NCLASS  40
#define BN_EPS  1e-5f

// ---------------- device scratch (no allocs allowed) ----------------
__device__ int   g_eidx[2 * EE];          // normalized int32 edge index (src | dst)
__device__ int   g_flag[1];               // dtype flag: 1 -> input was int32
__device__ int   g_deg[NN];
__device__ int   g_tmp[NN];               // block-inclusive scan
__device__ int   g_bsum[256];
__device__ int   g_boff[256];
__device__ int   g_off[NN + 1];
__device__ int   g_cur[NN];
__device__ int   g_csr[EE];

__device__ float g_agg [NN * NF];
__device__ float g_h1  [NN * NF];
__device__ float g_h2  [NN * NF];
__device__ float g_p   [NN * 80];         // conv2 projected [P_l | P_r]
__device__ float g_oraw[NN * NCLASS];
__device__ float g_bc1 [256 * 128];       // k-major concat weights conv1
__device__ float g_bcx [256 * 128];       // conv_x
__device__ float g_bc2 [128 * 128];       // conv2 (cols 0..39 W2l, 40..79 W2r, rest 0)
__device__ float g_stats[256];            // [sum(0..127) | sumsq(128..255)]
__device__ float g_scale[128];
__device__ float g_shift[128];

// ---------------- edge-index dtype detect + convert ----------------
__global__ void detect_dtype_kernel(const void* p, int E, int n_nodes) {
    if (threadIdx.x == 0 && blockIdx.x == 0) {
        const long long* q = (const long long*)p;
        int m = E < 512 ? E : 512;
        int bad = 0;
        for (int i = 0; i < m; i++) {
            long long v = q[i];
            if (v < 0 || v >= (long long)n_nodes) bad = 1;
        }
        g_flag[0] = bad;  // bad under int64 view => data is really int32
    }
}

__global__ void convert_idx_kernel(const void* p, int twoE) {
    int is32 = g_flag[0];
    for (int i = blockIdx.x * blockDim.x + threadIdx.x; i < twoE;
         i += gridDim.x * blockDim.x) {
        int v;
        if (is32) v = ((const int*)p)[i];
        else      v = (int)((const long long*)p)[i];
        g_eidx[i] = v;
    }
}

// ---------------- CSR build ----------------
__global__ void zero_int_kernel(int* p, int n) {
    for (int i = blockIdx.x * blockDim.x + threadIdx.x; i < n;
         i += gridDim.x * blockDim.x) p[i] = 0;
}

__global__ void count_deg_kernel(int E) {
    const int* dst = g_eidx + E;
    for (int e = blockIdx.x * blockDim.x + threadIdx.x; e < E;
         e += gridDim.x * blockDim.x) {
        atomicAdd(&g_deg[dst[e]], 1);
    }
}

__global__ void scan1_kernel(int n) {
    __shared__ int sh[512];
    int i = blockIdx.x * 512 + threadIdx.x;
    int v = (i < n) ? g_deg[i] : 0;
    sh[threadIdx.x] = v;
    __syncthreads();
    #pragma unroll
    for (int s = 1; s < 512; s <<= 1) {
        int t = (threadIdx.x >= s) ? sh[threadIdx.x - s] : 0;
        __syncthreads();
        sh[threadIdx.x] += t;
        __syncthreads();
    }
    if (i < n) g_tmp[i] = sh[threadIdx.x];
    if (threadIdx.x == 511) g_bsum[blockIdx.x] = sh[511];
}

__global__ void scan2_kernel(int nb) {
    __shared__ int sh[256];
    int v = (threadIdx.x < nb) ? g_bsum[threadIdx.x] : 0;
    sh[threadIdx.x] = v;
    __syncthreads();
    #pragma unroll
    for (int s = 1; s < 256; s <<= 1) {
        int t = (threadIdx.x >= s) ? sh[threadIdx.x - s] : 0;
        __syncthreads();
        sh[threadIdx.x] += t;
        __syncthreads();
    }
    if (threadIdx.x < nb) g_boff[threadIdx.x] = sh[threadIdx.x] - v;  // exclusive
}

__global__ void scan3_kernel(int n) {
    for (int i = blockIdx.x * blockDim.x + threadIdx.x; i < n;
         i += gridDim.x * blockDim.x) {
        int incl = g_tmp[i] + g_boff[i >> 9];
        int excl = incl - g_deg[i];
        g_off[i] = excl;
        g_cur[i] = excl;
        if (i == n - 1) g_off[n] = incl;
    }
}

__global__ void fill_csr_kernel(int E) {
    const int* src = g_eidx;
    const int* dst = g_eidx + E;
    for (int e = blockIdx.x * blockDim.x + threadIdx.x; e < E;
         e += gridDim.x * blockDim.x) {
        int pos = atomicAdd(&g_cur[dst[e]], 1);
        g_csr[pos] = src[e];
    }
}

// ---------------- weight prep (k-major concat) ----------------
__global__ void prep_dual_w_kernel(const float* __restrict__ Wl,
                                   const float* __restrict__ Wr,
                                   float* __restrict__ out) {  // [256][128]
    for (int idx = blockIdx.x * blockDim.x + threadIdx.x; idx < 256 * 128;
         idx += gridDim.x * blockDim.x) {
        int k = idx >> 7, j = idx & 127;
        out[idx] = (k < 128) ? Wl[j * 128 + k] : Wr[j * 128 + (k - 128)];
    }
}

__global__ void prep_w2_kernel(const float* __restrict__ W2l,
                               const float* __restrict__ W2r) {  // g_bc2[128][128]
    for (int idx = blockIdx.x * blockDim.x + threadIdx.x; idx < 128 * 128;
         idx += gridDim.x * blockDim.x) {
        int k = idx >> 7, j = idx & 127;
        float v = 0.f;
        if (j < 40)       v = W2l[j * 128 + k];
        else if (j < 80)  v = W2r[(j - 40) * 128 + k];
        g_bc2[idx] = v;
    }
}

// ---------------- mean aggregation, warp-per-node, float4 ----------------
__global__ __launch_bounds__(256)
void agg_mean128_kernel(const float* __restrict__ X,
                        float* __restrict__ OUT, int n) {
    int warp = threadIdx.x >> 5;
    int lane = threadIdx.x & 31;
    int node = blockIdx.x * 8 + warp;
    if (node >= n) return;
    const float4* X4 = (const float4*)X;
    int s0 = g_off[node], s1 = g_off[node + 1];
    float4 acc = make_float4(0.f, 0.f, 0.f, 0.f);
    for (int base = s0; base < s1; base += 32) {
        int c = s1 - base; if (c > 32) c = 32;
        int nbv = (lane < c) ? g_csr[base + lane] : 0;
        int j = 0;
        for (; j + 4 <= c; j += 4) {
            int v0 = __shfl_sync(0xffffffffu, nbv, j);
            int v1 = __shfl_sync(0xffffffffu, nbv, j + 1);
            int v2 = __shfl_sync(0xffffffffu, nbv, j + 2);
            int v3 = __shfl_sync(0xffffffffu, nbv, j + 3);
            float4 x0 = X4[(size_t)v0 * 32 + lane];
            float4 x1 = X4[(size_t)v1 * 32 + lane];
            float4 x2 = X4[(size_t)v2 * 32 + lane];
            float4 x3 = X4[(size_t)v3 * 32 + lane];
            acc.x += x0.x + x1.x + x2.x + x3.x;
            acc.y += x0.y + x1.y + x2.y + x3.y;
            acc.z += x0.z + x1.z + x2.z + x3.z;
            acc.w += x0.w + x1.w + x2.w + x3.w;
        }
        for (; j < c; j++) {
            int v = __shfl_sync(0xffffffffu, nbv, j);
            float4 x = X4[(size_t)v * 32 + lane];
            acc.x += x.x; acc.y += x.y; acc.z += x.z; acc.w += x.w;
        }
    }
    int deg = s1 - s0;
    float inv = deg > 0 ? 1.f / (float)deg : 0.f;
    acc.x *= inv; acc.y *= inv; acc.z *= inv; acc.w *= inv;
    ((float4*)OUT)[(size_t)node * 32 + lane] = acc;
}

// ---------------- conv2: agg 40-wide + combine + bias ----------------
__global__ __launch_bounds__(256)
void agg40_kernel(const float* __restrict__ b2, int n) {
    int warp = threadIdx.x >> 5;
    int lane = threadIdx.x & 31;
    int node = blockIdx.x * 8 + warp;
    if (node >= n) return;
    const float4* P4 = (const float4*)g_p;   // row = 20 float4 (80 floats)
    int s0 = g_off[node], s1 = g_off[node + 1];
    float4 acc = make_float4(0.f, 0.f, 0.f, 0.f);
    for (int base = s0; base < s1; base += 32) {
        int c = s1 - base; if (c > 32) c = 32;
        int nbv = (lane < c) ? g_csr[base + lane] : 0;
        int j = 0;
        for (; j + 4 <= c; j += 4) {
            int v0 = __shfl_sync(0xffffffffu, nbv, j);
            int v1 = __shfl_sync(0xffffffffu, nbv, j + 1);
            int v2 = __shfl_sync(0xffffffffu, nbv, j + 2);
            int v3 = __shfl_sync(0xffffffffu, nbv, j + 3);
            if (lane < 10) {
                float4 x0 = P4[(size_t)v0 * 20 + lane];
                float4 x1 = P4[(size_t)v1 * 20 + lane];
                float4 x2 = P4[(size_t)v2 * 20 + lane];
                float4 x3 = P4[(size_t)v3 * 20 + lane];
                acc.x += x0.x + x1.x + x2.x + x3.x;
                acc.y += x0.y + x1.y + x2.y + x3.y;
                acc.z += x0.z + x1.z + x2.z + x3.z;
                acc.w += x0.w + x1.w + x2.w + x3.w;
            }
        }
        for (; j < c; j++) {
            int v = __shfl_sync(0xffffffffu, nbv, j);
            if (lane < 10) {
                float4 x = P4[(size_t)v * 20 + lane];
                acc.x += x.x; acc.y += x.y; acc.z += x.z; acc.w += x.w;
            }
        }
    }
    if (lane < 10) {
        int deg = s1 - s0;
        float inv = deg > 0 ? 1.f / (float)deg : 0.f;
        float4 r  = P4[(size_t)node * 20 + 10 + lane];
        float4 bb = ((const float4*)b2)[lane];
        float4 o;
        o.x = acc.x * inv + r.x + bb.x;
        o.y = acc.y * inv + r.y + bb.y;
        o.z = acc.z * inv + r.z + bb.z;
        o.w = acc.w * inv + r.w + bb.w;
        ((float4*)g_oraw)[(size_t)node * 10 + lane] = o;
    }
}

// ---------------- f32x2 packed GEMM ----------------
// C[M,ncol] = concat(A1,A2)[M,K] @ B[K,128]; optional bias, relu,
// BN apply on A-load (bnA), fused column stats (do_stats).
__global__ __launch_bounds__(256)
void gemm_f32x2_kernel(const float* __restrict__ A1, const float* __restrict__ A2,
                       const float* __restrict__ B, const float* __restrict__ bias,
                       float* __restrict__ C, int M, int K, int ncol, int ldc,
                       int relu, int bnA, int do_stats) {
    __shared__ __align__(16) float As[16][132];
    __shared__ __align__(16) float Bs[16][128];
    __shared__ float s_sum[128];
    __shared__ float s_sq[128];

    const int tid = threadIdx.x;
    const int tx = tid & 15, ty = tid >> 4;
    const int row0 = blockIdx.x * 128;

    unsigned long long acc[8][4];
    #pragma unroll
    for (int m = 0; m < 8; m++)
        #pragma unroll
        for (int j = 0; j < 4; j++) acc[m][j] = 0ULL;

    auto loadA = [&](int k0, int l, float4& out) {
        int f = l * 256 + tid;
        int r = f >> 2, q = f & 3;
        int rg = row0 + r;
        int kg = k0 + q * 4;
        const float* Ap = (kg < 128) ? A1 : A2;
        int kloc = kg & 127;
        float4 v = make_float4(0.f, 0.f, 0.f, 0.f);
        if (rg < M) v = *(const float4*)&Ap[(size_t)rg * 128 + kloc];
        if (bnA) {
            float4 sc = *(const float4*)&g_scale[kg];
            float4 sh = *(const float4*)&g_shift[kg];
            v.x = fmaxf(v.x * sc.x + sh.x, 0.f);
            v.y = fmaxf(v.y * sc.y + sh.y, 0.f);
            v.z = fmaxf(v.z * sc.z + sh.z, 0.f);
            v.w = fmaxf(v.w * sc.w + sh.w, 0.f);
        }
        out = v;
    };
    auto loadB = [&](int k0, int l, float4& out) {
        int f = l * 256 + tid;
        int kk = f >> 5, j4 = f & 31;
        out = *(const float4*)&B[(size_t)(k0 + kk) * 128 + j4 * 4];
    };

    float4 aA[2], bB[2];
    loadA(0, 0, aA[0]); loadA(0, 1, aA[1]);
    loadB(0, 0, bB[0]); loadB(0, 1, bB[1]);

    for (int k0 = 0; k0 < K; k0 += 16) {
        // store current tile
        #pragma unroll
        for (int l = 0; l < 2; l++) {
            int f = l * 256 + tid;
            int r = f >> 2, q = f & 3;
            As[q * 4 + 0][r] = aA[l].x;
            As[q * 4 + 1][r] = aA[l].y;
            As[q * 4 + 2][r] = aA[l].z;
            As[q * 4 + 3][r] = aA[l].w;
            int kk = f >> 5, j4 = f & 31;
            *(float4*)&Bs[kk][j4 * 4] = bB[l];
        }
        __syncthreads();

        float4 aN[2], bN[2];
        if (k0 + 16 < K) {
            loadA(k0 + 16, 0, aN[0]); loadA(k0 + 16, 1, aN[1]);
            loadB(k0 + 16, 0, bN[0]); loadB(k0 + 16, 1, bN[1]);
        }

        #pragma unroll
        for (int kk = 0; kk < 16; kk++) {
            float4 ra0 = *(const float4*)&As[kk][ty * 8];
            float4 ra1 = *(const float4*)&As[kk][ty * 8 + 4];
            ulonglong2 rb0 = *(const ulonglong2*)&Bs[kk][tx * 4];
            ulonglong2 rb1 = *(const ulonglong2*)&Bs[kk][tx * 4 + 64];
            unsigned long long rb[4] = { rb0.x, rb0.y, rb1.x, rb1.y };
            float ra[8] = { ra0.x, ra0.y, ra0.z, ra0.w,
                            ra1.x, ra1.y, ra1.z, ra1.w };
            #pragma unroll
            for (int m = 0; m < 8; m++) {
                unsigned long long ap;
                asm("mov.b64 %0, {%1, %1};" : "=l"(ap) : "f"(ra[m]));
                #pragma unroll
                for (int j = 0; j < 4; j++)
                    asm("fma.rn.f32x2 %0, %1, %2, %0;"
                        : "+l"(acc[m][j]) : "l"(ap), "l"(rb[j]));
            }
        }
        __syncthreads();
        aA[0] = aN[0]; aA[1] = aN[1]; bB[0] = bN[0]; bB[1] = bN[1];
    }

    // epilogue
    float bv[8];
    #pragma unroll
    for (int h = 0; h < 8; h++) {
        int c = (h < 4) ? tx * 4 + h : 64 + tx * 4 + (h - 4);
        bv[h] = (bias && c < ncol) ? bias[c] : 0.f;
    }
    float colsum[8], colsq[8];
    #pragma unroll
    for (int h = 0; h < 8; h++) { colsum[h] = 0.f; colsq[h] = 0.f; }

    #pragma unroll
    for (int m = 0; m < 8; m++) {
        int rg = row0 + ty * 8 + m;
        bool valid = rg < M;
        float vr[8];
        #pragma unroll
        for (int j = 0; j < 4; j++)
            asm("mov.b64 {%0, %1}, %2;"
                : "=f"(vr[2 * j]), "=f"(vr[2 * j + 1]) : "l"(acc[m][j]));
        #pragma unroll
        for (int h = 0; h < 8; h++) {
            int c = (h < 4) ? tx * 4 + h : 64 + tx * 4 + (h - 4);
            float v = vr[h] + bv[h];
            if (relu) v = fmaxf(v, 0.f);
            if (valid && c < ncol) C[(size_t)rg * ldc + c] = v;
            if (do_stats && valid) { colsum[h] += v; colsq[h] += v * v; }
        }
    }

    if (do_stats) {
        __syncthreads();
        if (tid < 128) { s_sum[tid] = 0.f; s_sq[tid] = 0.f; }
        __syncthreads();
        #pragma unroll
        for (int h = 0; h < 8; h++) {
            int c = (h < 4) ? tx * 4 + h : 64 + tx * 4 + (h - 4);
            atomicAdd(&s_sum[c], colsum[h]);
            atomicAdd(&s_sq[c], colsq[h]);
        }
        __syncthreads();
        if (tid < 128) {
            atomicAdd(&g_stats[tid], s_sum[tid]);
            atomicAdd(&g_stats[128 + tid], s_sq[tid]);
        }
    }
}

// ---------------- BatchNorm ----------------
__global__ void zero_stats_kernel() {
    if (threadIdx.x < 256) g_stats[threadIdx.x] = 0.f;
}

__global__ void bn_stats_kernel(const float* __restrict__ X, int M, int F, int ld) {
    int col = threadIdx.x;
    if (col >= F) return;
    float s = 0.f, s2 = 0.f;
    for (int r = blockIdx.x; r < M; r += gridDim.x) {
        float v = X[(size_t)r * ld + col];
        s += v; s2 += v * v;
    }
    atomicAdd(&g_stats[col], s);
    atomicAdd(&g_stats[128 + col], s2);
}

__global__ void bn_finalize_kernel(const float* __restrict__ gamma,
                                   const float* __restrict__ beta,
                                   int F, float invM) {
    int c = threadIdx.x;
    if (c < F) {
        float mu  = g_stats[c] * invM;
        float var = g_stats[128 + c] * invM - mu * mu;
        float sc  = gamma[c] * rsqrtf(var + BN_EPS);
        g_scale[c] = sc;
        g_shift[c] = beta[c] - mu * sc;
    }
}

__global__ void bn_apply_kernel(const float* __restrict__ X, float* __restrict__ Y,
                                int total, int F, int relu) {
    for (int i = blockIdx.x * blockDim.x + threadIdx.x; i < total;
         i += gridDim.x * blockDim.x) {
        int c = i % F;
        float v = X[i] * g_scale[c] + g_shift[c];
        if (relu) v = fmaxf(v, 0.f);
        Y[i] = v;
    }
}

// ---------------- launcher ----------------
extern "C" void kernel_launch(void* const* d_in, const int* in_sizes, int n_in,
                              void* d_out, int out_size) {
    const float* x   = (const float*)d_in[0];
    const void*  ei  = d_in[1];
    const float* W1l = (const float*)d_in[2];
    const float* b1  = (const float*)d_in[3];
    const float* W1r = (const float*)d_in[4];
    const float* Wxl = (const float*)d_in[5];
    const float* bx  = (const float*)d_in[6];
    const float* Wxr = (const float*)d_in[7];
    const float* W2l = (const float*)d_in[8];
    const float* b2  = (const float*)d_in[9];
    const float* W2r = (const float*)d_in[10];
    const float* g3  = (const float*)d_in[11];
    const float* be3 = (const float*)d_in[12];
    const float* g2  = (const float*)d_in[13];
    const float* be2 = (const float*)d_in[14];
    float* out = (float*)d_out;

    const int N    = in_sizes[0] / NF;      // 100000
    const int twoE = in_sizes[1];
    const int E    = twoE / 2;              // 1600000

    float *p_agg, *p_h1, *p_h2, *p_p, *p_bc1, *p_bcx, *p_bc2, *p_oraw;
    int   *p_deg;
    cudaGetSymbolAddress((void**)&p_agg,  g_agg);
    cudaGetSymbolAddress((void**)&p_h1,   g_h1);
    cudaGetSymbolAddress((void**)&p_h2,   g_h2);
    cudaGetSymbolAddress((void**)&p_p,    g_p);
    cudaGetSymbolAddress((void**)&p_oraw, g_oraw);
    cudaGetSymbolAddress((void**)&p_bc1,  g_bc1);
    cudaGetSymbolAddress((void**)&p_bcx,  g_bcx);
    cudaGetSymbolAddress((void**)&p_bc2,  g_bc2);
    cudaGetSymbolAddress((void**)&p_deg,  g_deg);

    const int nb = (N + 511) / 512;
    const int gemm_blocks = (N + 127) / 128;
    const int agg_blocks  = (N + 7) / 8;

    // --- edge index normalize ---
    detect_dtype_kernel<<<1, 32>>>(ei, E, N);
    convert_idx_kernel<<<2048, 256>>>(ei, twoE);

    // --- CSR build ---
    zero_int_kernel<<<512, 256>>>(p_deg, N);
    count_deg_kernel<<<2048, 256>>>(E);
    scan1_kernel<<<nb, 512>>>(N);
    scan2_kernel<<<1, 256>>>(nb);
    scan3_kernel<<<512, 256>>>(N);
    fill_csr_kernel<<<2048, 256>>>(E);

    // --- weight prep ---
    prep_dual_w_kernel<<<128, 256>>>(W1l, W1r, p_bc1);
    prep_dual_w_kernel<<<128, 256>>>(Wxl, Wxr, p_bcx);
    prep_w2_kernel<<<64, 256>>>(W2l, W2r);

    // --- conv1 + relu ---
    agg_mean128_kernel<<<agg_blocks, 256>>>(x, p_agg, N);
    gemm_f32x2_kernel<<<gemm_blocks, 256>>>(p_agg, x, p_bc1, b1, p_h1,
                                            N, 256, 128, 128, 1, 0, 0);

    // --- conv_x (BN3 stats fused into GEMM epilogue) ---
    agg_mean128_kernel<<<agg_blocks, 256>>>(p_h1, p_agg, N);
    zero_stats_kernel<<<1, 256>>>();
    gemm_f32x2_kernel<<<gemm_blocks, 256>>>(p_agg, p_h1, p_bcx, bx, p_h2,
                                            N, 256, 128, 128, 0, 0, 1);
    bn_finalize_kernel<<<1, 128>>>(g3, be3, 128, 1.f / (float)N);

    // --- conv2: project (BN3 apply + relu fused on A-load), then aggregate ---
    gemm_f32x2_kernel<<<gemm_blocks, 256>>>(p_h2, p_h2, p_bc2, nullptr, p_p,
                                            N, 128, 80, 80, 0, 1, 0);
    agg40_kernel<<<agg_blocks, 256>>>(b2, N);

    // --- BN2 -> output ---
    zero_stats_kernel<<<1, 256>>>();
    bn_stats_kernel<<<1024, 64>>>(p_oraw, N, NCLASS, NCLASS);
    bn_finalize_kernel<<<1, 64>>>(g2, be2, NCLASS, 1.f / (float)N);
    bn_apply_kernel<<<2048, 256>>>(p_oraw, out, N * NCLASS, NCLASS, 0);
}